// round 2
// baseline (speedup 1.0000x reference)
#include <cuda_runtime.h>
#include <cstdint>

// Block-diagonal linear: y[n, b*64+j] = sum_{k<64} x[n, b*64+k] * w[b*64+j, b*64+k]
// 64 independent [8192,64]x[64,64]^T GEMMs.
// tf32 mma.sync with 3-term split (hi*hi + hi*lo + lo*hi) for fp32-grade accuracy.

#define N_FEAT     4096
#define BLK        64
#define NBLK       64
#define ROWS_TILE  64
#define THREADS    128
#define XS         68   // padded smem stride (floats): bank = (4r+c)%32 -> conflict-free frags
#define WS         68

__device__ __forceinline__ void split_tf32(float v, uint32_t& hi, uint32_t& lo) {
    uint32_t h;
    asm("cvt.rna.tf32.f32 %0, %1;" : "=r"(h) : "f"(v));
    float lf = v - __uint_as_float(h);
    uint32_t l;
    asm("cvt.rna.tf32.f32 %0, %1;" : "=r"(l) : "f"(lf));
    hi = h; lo = l;
}

__device__ __forceinline__ void mma_tf32(float c[4],
                                         uint32_t a0, uint32_t a1, uint32_t a2, uint32_t a3,
                                         uint32_t b0, uint32_t b1) {
    asm volatile(
        "mma.sync.aligned.m16n8k8.row.col.f32.tf32.tf32.f32 "
        "{%0,%1,%2,%3}, {%4,%5,%6,%7}, {%8,%9}, {%0,%1,%2,%3};"
        : "+f"(c[0]), "+f"(c[1]), "+f"(c[2]), "+f"(c[3])
        : "r"(a0), "r"(a1), "r"(a2), "r"(a3), "r"(b0), "r"(b1));
}

__global__ __launch_bounds__(THREADS)
void sl_blockdiag_kernel(const float* __restrict__ x,
                         const float* __restrict__ w,
                         float* __restrict__ out) {
    __shared__ float sX[ROWS_TILE * XS];
    __shared__ float sW[BLK * WS];

    const int b  = blockIdx.x % NBLK;      // which diagonal block
    const int rt = blockIdx.x / NBLK;      // which 64-row tile

    const int tid = threadIdx.x;
    const size_t colbase = (size_t)b * BLK;
    const size_t row0g   = (size_t)rt * ROWS_TILE;

    // --- stage W_b (64x64 f32) into padded shared ---
    #pragma unroll
    for (int i = tid; i < BLK * 16; i += THREADS) {
        int j = i >> 4, q = i & 15;   // row j, float4 q
        float4 v = *(const float4*)(w + (colbase + j) * N_FEAT + colbase + q * 4);
        *(float4*)(sW + j * WS + q * 4) = v;
    }
    // --- stage X tile (64x64 f32) ---
    #pragma unroll
    for (int i = tid; i < ROWS_TILE * 16; i += THREADS) {
        int r = i >> 4, q = i & 15;
        float4 v = *(const float4*)(x + (row0g + r) * N_FEAT + colbase + q * 4);
        *(float4*)(sX + r * XS + q * 4) = v;
    }
    __syncthreads();

    const int wid  = tid >> 5;
    const int lane = tid & 31;
    const int g    = lane >> 2;   // groupID (0..7)
    const int tq   = lane & 3;    // thread-in-group
    const int m0   = wid * 16;    // this warp's 16 rows within the tile

    float c[8][4];
    #pragma unroll
    for (int i = 0; i < 8; i++)
        #pragma unroll
        for (int j = 0; j < 4; j++) c[i][j] = 0.f;

    for (int ks = 0; ks < 8; ks++) {
        const int k0 = ks * 8;

        // A fragment (rows m0+g / m0+g+8, cols k0+tq / k0+tq+4)
        float ar0 = sX[(m0 + g)     * XS + k0 + tq];
        float ar1 = sX[(m0 + g + 8) * XS + k0 + tq];
        float ar2 = sX[(m0 + g)     * XS + k0 + tq + 4];
        float ar3 = sX[(m0 + g + 8) * XS + k0 + tq + 4];
        uint32_t ah[4], al[4];
        split_tf32(ar0, ah[0], al[0]);
        split_tf32(ar1, ah[1], al[1]);
        split_tf32(ar2, ah[2], al[2]);
        split_tf32(ar3, ah[3], al[3]);

        // B fragments for all 8 n-tiles at this k-step.
        // mma .col B: b0 = B[k=tq][n=g] = W[n][k] -> sW[(nt*8+g)][k0+tq]
        uint32_t bh[8][2], bl[8][2];
        #pragma unroll
        for (int nt = 0; nt < 8; nt++) {
            float br0 = sW[(nt * 8 + g) * WS + k0 + tq];
            float br1 = sW[(nt * 8 + g) * WS + k0 + tq + 4];
            split_tf32(br0, bh[nt][0], bl[nt][0]);
            split_tf32(br1, bh[nt][1], bl[nt][1]);
        }

        #pragma unroll
        for (int nt = 0; nt < 8; nt++) {
            mma_tf32(c[nt], ah[0], ah[1], ah[2], ah[3], bh[nt][0], bh[nt][1]);
            mma_tf32(c[nt], ah[0], ah[1], ah[2], ah[3], bl[nt][0], bl[nt][1]);
            mma_tf32(c[nt], al[0], al[1], al[2], al[3], bh[nt][0], bh[nt][1]);
        }
    }

    // --- store: C fragment rows g/g+8, cols 2*tq / 2*tq+1 per n-tile ---
    const size_t row = row0g + m0 + g;
    #pragma unroll
    for (int nt = 0; nt < 8; nt++) {
        size_t col = colbase + nt * 8 + tq * 2;
        *(float2*)(out + row * N_FEAT + col)       = make_float2(c[nt][0], c[nt][1]);
        *(float2*)(out + (row + 8) * N_FEAT + col) = make_float2(c[nt][2], c[nt][3]);
    }
}

extern "C" void kernel_launch(void* const* d_in, const int* in_sizes, int n_in,
                              void* d_out, int out_size) {
    const float* x = (const float*)d_in[0];
    const float* w = (const float*)d_in[1];
    float* out = (float*)d_out;

    const int n_rows = in_sizes[0] / N_FEAT;        // 8192
    const int row_tiles = n_rows / ROWS_TILE;       // 128

    dim3 grid(NBLK * row_tiles);                    // 8192 CTAs
    sl_blockdiag_kernel<<<grid, THREADS>>>(x, w, out);
}

// round 3
// speedup vs baseline: 1.4348x; 1.4348x over previous
#include <cuda_runtime.h>
#include <cuda_fp16.h>
#include <cstdint>

// Block-diagonal linear: y[n, b*64+j] = sum_{k<64} x[n, b*64+k] * w[b*64+j, b*64+k]
// 64 independent [8192,64]x[64,64]^T GEMMs.
// fp16 mma.sync m16n8k16 with 2-way hi/lo split, 3 terms (hh + hl + lh): ~1e-6 rel err.
// Splits precomputed into shared (packed f16x2) so the mainloop is pure LDS + HMMA.

#define N_FEAT     4096
#define BLK        64
#define NBLK       64
#define ROWS_TILE  64
#define THREADS    128
#define XSP        36   // u32 stride: (36*g + tq) % 32 = (4g+tq)%32 -> 32 distinct banks

__device__ __forceinline__ void split_pack2(float a, float b, uint32_t& hi, uint32_t& lo) {
    __half ha = __float2half_rn(a), hb = __float2half_rn(b);
    __half la = __float2half_rn(a - __half2float(ha));
    __half lb = __float2half_rn(b - __half2float(hb));
    __half2 H = __halves2half2(ha, hb);   // x = even k (low), y = odd k (high)
    __half2 L = __halves2half2(la, lb);
    hi = *(uint32_t*)&H;
    lo = *(uint32_t*)&L;
}

__device__ __forceinline__ void mma_f16(float c[4],
                                        uint32_t a0, uint32_t a1, uint32_t a2, uint32_t a3,
                                        uint32_t b0, uint32_t b1) {
    asm volatile(
        "mma.sync.aligned.m16n8k16.row.col.f32.f16.f16.f32 "
        "{%0,%1,%2,%3}, {%4,%5,%6,%7}, {%8,%9}, {%0,%1,%2,%3};"
        : "+f"(c[0]), "+f"(c[1]), "+f"(c[2]), "+f"(c[3])
        : "r"(a0), "r"(a1), "r"(a2), "r"(a3), "r"(b0), "r"(b1));
}

__global__ __launch_bounds__(THREADS)
void sl_blockdiag_kernel(const float* __restrict__ x,
                         const float* __restrict__ w,
                         float* __restrict__ out) {
    __shared__ uint32_t sXh[ROWS_TILE * XSP], sXl[ROWS_TILE * XSP];
    __shared__ uint32_t sWh[BLK * XSP],       sWl[BLK * XSP];

    const int b  = blockIdx.x % NBLK;      // diagonal block
    const int rt = blockIdx.x / NBLK;      // 64-row tile

    const int tid = threadIdx.x;
    const size_t colbase = (size_t)b * BLK;
    const size_t row0g   = (size_t)rt * ROWS_TILE;

    // --- stage + split W_b (64x64) into packed f16x2 hi/lo shared ---
    #pragma unroll
    for (int i = tid; i < BLK * 16; i += THREADS) {
        int r = i >> 4, q = i & 15;   // row r, float4 q (k = 4q..4q+3 -> packed cols 2q, 2q+1)
        float4 v = *(const float4*)(w + (colbase + r) * N_FEAT + colbase + q * 4);
        uint32_t h0, l0, h1, l1;
        split_pack2(v.x, v.y, h0, l0);
        split_pack2(v.z, v.w, h1, l1);
        sWh[r * XSP + q * 2]     = h0;  sWl[r * XSP + q * 2]     = l0;
        sWh[r * XSP + q * 2 + 1] = h1;  sWl[r * XSP + q * 2 + 1] = l1;
    }
    // --- stage + split X tile (64x64) ---
    #pragma unroll
    for (int i = tid; i < ROWS_TILE * 16; i += THREADS) {
        int r = i >> 4, q = i & 15;
        float4 v = *(const float4*)(x + (row0g + r) * N_FEAT + colbase + q * 4);
        uint32_t h0, l0, h1, l1;
        split_pack2(v.x, v.y, h0, l0);
        split_pack2(v.z, v.w, h1, l1);
        sXh[r * XSP + q * 2]     = h0;  sXl[r * XSP + q * 2]     = l0;
        sXh[r * XSP + q * 2 + 1] = h1;  sXl[r * XSP + q * 2 + 1] = l1;
    }
    __syncthreads();

    const int wid  = tid >> 5;
    const int lane = tid & 31;
    const int g    = lane >> 2;   // groupID (0..7)
    const int tq   = lane & 3;    // thread-in-group
    const int m0   = wid * 16;    // this warp's 16 rows

    float c[8][4];
    #pragma unroll
    for (int i = 0; i < 8; i++)
        #pragma unroll
        for (int j = 0; j < 4; j++) c[i][j] = 0.f;

    // K=64 -> 4 k-steps of 16 (8 packed f16x2 columns each)
    #pragma unroll
    for (int ks = 0; ks < 4; ks++) {
        const int kp0 = ks * 8;   // packed column base

        // A fragment (m16n8k16): a0={r=g,k=2tq..}, a1={r=g+8}, a2={r=g,k=2tq+8..}, a3={r=g+8}
        const int rowA0 = (m0 + g) * XSP + kp0 + tq;
        const int rowA1 = (m0 + g + 8) * XSP + kp0 + tq;
        uint32_t ah0 = sXh[rowA0],     ah1 = sXh[rowA1];
        uint32_t ah2 = sXh[rowA0 + 4], ah3 = sXh[rowA1 + 4];
        uint32_t al0 = sXl[rowA0],     al1 = sXl[rowA1];
        uint32_t al2 = sXl[rowA0 + 4], al3 = sXl[rowA1 + 4];

        #pragma unroll
        for (int nt = 0; nt < 8; nt++) {
            // B fragment (.col): b0={k=2tq..,n=g}, b1={k=2tq+8..,n=g};  B[k][n]=W[n][k]
            const int rowB = (nt * 8 + g) * XSP + kp0 + tq;
            uint32_t bh0 = sWh[rowB], bh1 = sWh[rowB + 4];
            uint32_t bl0 = sWl[rowB], bl1 = sWl[rowB + 4];

            mma_f16(c[nt], ah0, ah1, ah2, ah3, bh0, bh1);   // hi*hi
            mma_f16(c[nt], ah0, ah1, ah2, ah3, bl0, bl1);   // hi*lo
            mma_f16(c[nt], al0, al1, al2, al3, bh0, bh1);   // lo*hi
        }
    }

    // --- store: C rows g/g+8, cols 2tq/2tq+1 per n-tile ---
    const size_t row = row0g + m0 + g;
    #pragma unroll
    for (int nt = 0; nt < 8; nt++) {
        size_t col = colbase + nt * 8 + tq * 2;
        *(float2*)(out + row * N_FEAT + col)       = make_float2(c[nt][0], c[nt][1]);
        *(float2*)(out + (row + 8) * N_FEAT + col) = make_float2(c[nt][2], c[nt][3]);
    }
}

extern "C" void kernel_launch(void* const* d_in, const int* in_sizes, int n_in,
                              void* d_out, int out_size) {
    const float* x = (const float*)d_in[0];
    const float* w = (const float*)d_in[1];
    float* out = (float*)d_out;

    const int n_rows = in_sizes[0] / N_FEAT;        // 8192
    const int row_tiles = n_rows / ROWS_TILE;       // 128

    dim3 grid(NBLK * row_tiles);                    // 8192 CTAs
    sl_blockdiag_kernel<<<grid, THREADS>>>(x, w, out);
}